// round 13
// baseline (speedup 1.0000x reference)
#include <cuda_runtime.h>
#include <cuda_fp16.h>

// SpatialTransformer: 3D trilinear warp, smem-tiled, ILP-4, fp16 z-pair tile,
// halo 2 on ALL axes -> tile 20x20x22 half2 = 35.2 KB -> 6 blocks/SM.
// (R12 = z-halo 4, 38.4 KB, 5 blocks/SM, 69.7us.)
//
// Tile entry (x,y,e) = __half2( v[z0-2+e], v[z0-2+e+1] ), e in [0..19],
// covering iz0 in [z0-2 .. z0+17]. A voxel's 8 corner loads are 4 LDS.32.
// Weights fp32. Out-of-tile voxels (~1.8%) take the exact fp32 fully-clamped
// global fallback.

#define DX 160
#define DY 192
#define DZ 160
#define NB 2
#define TS 16
#define SX 20           // x entries: [x0-2 .. x0+17]
#define SY 20           // y entries: [y0-2 .. y0+17]
#define SZE 20          // z entries: e in [0..19] -> iz0 in [z0-2 .. z0+17]
#define SZPH 22         // padded entry stride (88B rows, 8B-aligned pairs)
#define SHALF2 (SX*SY*SZPH)   // 8800 half2 = 35200 B

extern __shared__ __half2 tile[];

__device__ __forceinline__ int iclamp(int v, int hi) {
    return min(max(v, 0), hi);
}

__device__ __forceinline__ unsigned pack_h2(float a, float b) {
    __half2 h = __floats2half2_rn(a, b);
    return *reinterpret_cast<unsigned*>(&h);
}

__global__ __launch_bounds__(256, 6)
void warp_h2occ6_kernel(const float* __restrict__ vol,
                        const float* __restrict__ trf,
                        float* __restrict__ out)
{
    const int tid = threadIdx.x;
    const int b  = blockIdx.z / (DX / TS);
    const int x0 = (blockIdx.z % (DX / TS)) * TS;
    const int y0 = blockIdx.y * TS;
    const int z0 = blockIdx.x * TS;

    const float* __restrict__ v = vol + (size_t)b * (DX * DY * DZ);
    const int xlo = x0 - 2, ylo = y0 - 2, zent0 = z0 - 2;   // entry 0 -> iz0 = z0-2

    // ---------------- cooperative tile fill ----------------
    if (z0 - 4 >= 0 && z0 + 19 <= DZ - 1) {
        // Load the aligned span v[z0-4 .. z0+19] as 6 float4 per (x,y) row.
        // Chunk c holds src[4c..4c+3]; entry e = (z - (z0-2)) gets pair
        // (src[e+2], src[e+3]). Chunk c covers entries 4c-2 .. 4c+1:
        //   e=4c-2:(x,y) e=4c-1:(y,z) e=4c:(z,w) e=4c+1:(w,next)
        // Stores are 8B uint2 at even entry offsets (row stride 88B).
        for (int idx = tid; idx < SX * SY * 6; idx += 256) {
            int c   = idx % 6;
            int row = idx / 6;
            int py  = row % SY;
            int px  = row / SY;
            int gx  = iclamp(xlo + px, DX - 1);
            int gy  = iclamp(ylo + py, DY - 1);
            const float* src = v + ((size_t)gx * DY + gy) * DZ + (z0 - 4);
            float4 val = __ldg(reinterpret_cast<const float4*>(src) + c);
            __half2* rowp = &tile[(px * SY + py) * SZPH];
            if (c == 0) {
                // entries 0:(z,w) 1:(w,next)
                float nxt = __ldg(src + 4);
                uint2 p; p.x = pack_h2(val.z, val.w); p.y = pack_h2(val.w, nxt);
                *reinterpret_cast<uint2*>(rowp + 0) = p;
            } else if (c == 5) {
                // entries 18:(x,y) 19:(y,z)
                uint2 p; p.x = pack_h2(val.x, val.y); p.y = pack_h2(val.y, val.z);
                *reinterpret_cast<uint2*>(rowp + 18) = p;
            } else {
                float nxt = __ldg(src + c * 4 + 4);
                uint2 p0; p0.x = pack_h2(val.x, val.y); p0.y = pack_h2(val.y, val.z);
                uint2 p1; p1.x = pack_h2(val.z, val.w); p1.y = pack_h2(val.w, nxt);
                *reinterpret_cast<uint2*>(rowp + (c * 4 - 2)) = p0;
                *reinterpret_cast<uint2*>(rowp + (c * 4    )) = p1;
            }
        }
    } else {
        // z-border: scalar, clamp baked into each pair.
        for (int idx = tid; idx < SX * SY * SZE; idx += 256) {
            int pz = idx % SZE;
            int r  = idx / SZE;
            int py = r % SY;
            int px = r / SY;
            int gx = iclamp(xlo + px, DX - 1);
            int gy = iclamp(ylo + py, DY - 1);
            const float* rowp = v + ((size_t)gx * DY + gy) * DZ;
            int gz0 = iclamp(zent0 + pz,     DZ - 1);
            int gz1 = iclamp(zent0 + pz + 1, DZ - 1);
            float a  = __ldg(rowp + gz0);
            float b2 = __ldg(rowp + gz1);
            tile[(px * SY + py) * SZPH + pz] = __floats2half2_rn(a, b2);
        }
    }
    __syncthreads();

    // ---------------- per-voxel warp, 4 z-voxels per thread ----------------
    const int zg = tid & 3;            // z quad (0..3)
    const int vy = (tid >> 2) & 15;    // 0..15
    const int xs = tid >> 6;           // 0..3
    const int gy = y0 + vy;
    const int zb = z0 + zg * 4;

    unsigned g = (unsigned)((((b * DX + x0 + xs) * DY + gy) * (DZ / 4))
                            + (z0 >> 2) + zg);
    const unsigned gstep = (unsigned)(DY * DZ);

    const float4* __restrict__ trf4 = reinterpret_cast<const float4*>(trf);
    float4* __restrict__ out4 = reinterpret_cast<float4*>(out);

#pragma unroll 1
    for (int it = 0; it < 4; ++it, g += gstep) {
        const int gx = x0 + it * 4 + xs;

        float4 t0 = __ldg(&trf4[g * 3u + 0u]);
        float4 t1 = __ldg(&trf4[g * 3u + 1u]);
        float4 t2 = __ldg(&trf4[g * 3u + 2u]);

        float tx[4] = {t0.x, t0.w, t1.z, t2.y};
        float ty[4] = {t0.y, t1.x, t1.w, t2.z};
        float tz[4] = {t0.z, t1.y, t2.x, t2.w};

        float4 res;
        float* rp = reinterpret_cast<float*>(&res);

#pragma unroll
        for (int j = 0; j < 4; ++j) {
            float lx = fminf(fmaxf((float)gx + tx[j],       0.0f), (float)(DX - 1));
            float ly = fminf(fmaxf((float)gy + ty[j],       0.0f), (float)(DY - 1));
            float lz = fminf(fmaxf((float)(zb + j) + tz[j], 0.0f), (float)(DZ - 1));

            int ix0 = __float2int_rd(lx);
            int iy0 = __float2int_rd(ly);
            int iz0 = __float2int_rd(lz);
            int ix1 = min(ix0 + 1, DX - 1);
            int iy1 = min(iy0 + 1, DY - 1);
            int iz1 = min(iz0 + 1, DZ - 1);

            float wx1 = (float)ix1 - lx;    // lower-corner weight (d1)
            float wy1 = (float)iy1 - ly;
            float wz1 = (float)iz1 - lz;
            float wx0 = 1.0f - wx1;
            float wy0 = 1.0f - wy1;
            float wz0 = 1.0f - wz1;

            float c00, c01, c10, c11;

            unsigned sux = (unsigned)(ix0 - xlo);
            unsigned suy = (unsigned)(iy0 - ylo);
            unsigned suz = (unsigned)(iz0 - zent0);

            if (sux <= (unsigned)(SX - 2) &&
                suy <= (unsigned)(SY - 2) &&
                suz <= (unsigned)(SZE - 1)) {
                int sy_step = (iy1 - iy0) * SZPH;           // 0 or 22
                int sx_step = (ix1 - ix0) * (SY * SZPH);
                const __half2* t00 = &tile[(sux * SY + suy) * SZPH + suz];
                float2 f00 = __half22float2(t00[0]);
                float2 f01 = __half22float2(t00[sy_step]);
                float2 f10 = __half22float2(t00[sx_step]);
                float2 f11 = __half22float2(t00[sx_step + sy_step]);
                c00 = f00.x * wz1 + f00.y * wz0;
                c01 = f01.x * wz1 + f01.y * wz0;
                c10 = f10.x * wz1 + f10.y * wz0;
                c11 = f11.x * wz1 + f11.y * wz0;
            } else {
                // exact fp32 global fallback (rare)
                const float* p00 = v + ((size_t)ix0 * DY + iy0) * DZ;
                const float* p01 = v + ((size_t)ix0 * DY + iy1) * DZ;
                const float* p10 = v + ((size_t)ix1 * DY + iy0) * DZ;
                const float* p11 = v + ((size_t)ix1 * DY + iy1) * DZ;
                c00 = __ldg(p00 + iz0) * wz1 + __ldg(p00 + iz1) * wz0;
                c01 = __ldg(p01 + iz0) * wz1 + __ldg(p01 + iz1) * wz0;
                c10 = __ldg(p10 + iz0) * wz1 + __ldg(p10 + iz1) * wz0;
                c11 = __ldg(p11 + iz0) * wz1 + __ldg(p11 + iz1) * wz0;
            }

            float c0 = c00 * wy1 + c01 * wy0;
            float c1 = c10 * wy1 + c11 * wy0;

            rp[j] = c0 * wx1 + c1 * wx0;
        }

        out4[g] = res;
    }
}

extern "C" void kernel_launch(void* const* d_in, const int* in_sizes, int n_in,
                              void* d_out, int out_size)
{
    const float* vol = (const float*)d_in[0];
    const float* trf = (const float*)d_in[1];
    float* out = (float*)d_out;

    cudaFuncSetAttribute(warp_h2occ6_kernel,
                         cudaFuncAttributeMaxDynamicSharedMemorySize,
                         SHALF2 * (int)sizeof(__half2));

    dim3 grid(DZ / TS, DY / TS, NB * (DX / TS));  // (10, 12, 20)
    warp_h2occ6_kernel<<<grid, 256, SHALF2 * sizeof(__half2)>>>(vol, trf, out);
}

// round 14
// speedup vs baseline: 1.1586x; 1.1586x over previous
#include <cuda_runtime.h>
#include <cuda_fp16.h>

// SpatialTransformer: 3D trilinear warp, smem-tiled, ILP-4, fp16 z-pair tile
// (R12 config: 20x20 xy, z-halo 4, 38.4 KB, 5 blocks/SM) with a CLAMP-FREE
// inner loop. Because the tile's halo is border-clamped at fill time, any
// sample whose floor is in-tile needs NO volume clamps: outside the border,
// both corners on an axis collapse to the same clamped plane, making the
// result weight-independent and equal to the reference. Floors outside the
// tile take the exact fully-clamped fp32 global fallback.
// Corner steps are compile-time constants -> LDS with immediate offsets.

#define DX 160
#define DY 192
#define DZ 160
#define NB 2
#define TS 16
#define SX 20           // x entries: [x0-2 .. x0+17]
#define SY 20           // y entries: [y0-2 .. y0+17]
#define SZE 23          // z entries: e in [0..22] -> iz0 in [z0-4 .. z0+18]
#define SZPH 24         // padded entry stride (96B rows, 16B-aligned)
#define SHALF2 (SX*SY*SZPH)   // 9600 half2 = 38400 B

extern __shared__ __half2 tile[];

__device__ __forceinline__ int iclamp(int v, int hi) {
    return min(max(v, 0), hi);
}

// Exact reference math, fully clamped, fp32 global gather (rare path).
__device__ __forceinline__ float fallback_exact(
    const float* __restrict__ v, float sx, float sy, float sz)
{
    float lx = fminf(fmaxf(sx, 0.0f), (float)(DX - 1));
    float ly = fminf(fmaxf(sy, 0.0f), (float)(DY - 1));
    float lz = fminf(fmaxf(sz, 0.0f), (float)(DZ - 1));
    int ix0 = __float2int_rd(lx);
    int iy0 = __float2int_rd(ly);
    int iz0 = __float2int_rd(lz);
    int ix1 = min(ix0 + 1, DX - 1);
    int iy1 = min(iy0 + 1, DY - 1);
    int iz1 = min(iz0 + 1, DZ - 1);
    float wx1 = (float)ix1 - lx, wy1 = (float)iy1 - ly, wz1 = (float)iz1 - lz;
    float wx0 = 1.0f - wx1, wy0 = 1.0f - wy1, wz0 = 1.0f - wz1;
    const float* p00 = v + ((size_t)ix0 * DY + iy0) * DZ;
    const float* p01 = v + ((size_t)ix0 * DY + iy1) * DZ;
    const float* p10 = v + ((size_t)ix1 * DY + iy0) * DZ;
    const float* p11 = v + ((size_t)ix1 * DY + iy1) * DZ;
    float c00 = __ldg(p00 + iz0) * wz1 + __ldg(p00 + iz1) * wz0;
    float c01 = __ldg(p01 + iz0) * wz1 + __ldg(p01 + iz1) * wz0;
    float c10 = __ldg(p10 + iz0) * wz1 + __ldg(p10 + iz1) * wz0;
    float c11 = __ldg(p11 + iz0) * wz1 + __ldg(p11 + iz1) * wz0;
    float c0 = c00 * wy1 + c01 * wy0;
    float c1 = c10 * wy1 + c11 * wy0;
    return c0 * wx1 + c1 * wx0;
}

__global__ __launch_bounds__(256, 5)
void warp_h2nc_kernel(const float* __restrict__ vol,
                      const float* __restrict__ trf,
                      float* __restrict__ out)
{
    const int tid = threadIdx.x;
    const int b  = blockIdx.z / (DX / TS);
    const int x0 = (blockIdx.z % (DX / TS)) * TS;
    const int y0 = blockIdx.y * TS;
    const int z0 = blockIdx.x * TS;

    const float* __restrict__ v = vol + (size_t)b * (DX * DY * DZ);
    const int xlo = x0 - 2, ylo = y0 - 2, zlo = z0 - 4;

    // ---------------- cooperative tile fill (clamped halo) ----------------
    if (zlo >= 0 && z0 + 19 <= DZ - 1) {
        // z-interior: per (x,y) row, 6 aligned float4 covering v[zlo..zlo+23].
        for (int idx = tid; idx < SX * SY * 6; idx += 256) {
            int c   = idx % 6;
            int row = idx / 6;
            int py  = row % SY;
            int px  = row / SY;
            int gx  = iclamp(xlo + px, DX - 1);
            int gy  = iclamp(ylo + py, DY - 1);
            const float* src = v + ((size_t)gx * DY + gy) * DZ + zlo;
            float4 val = __ldg(reinterpret_cast<const float4*>(src) + c);
            float nxt = (c < 5) ? __ldg(src + c * 4 + 4) : val.w;
            __half2 h0 = __floats2half2_rn(val.x, val.y);
            __half2 h1 = __floats2half2_rn(val.y, val.z);
            __half2 h2 = __floats2half2_rn(val.z, val.w);
            __half2 h3 = __floats2half2_rn(val.w, nxt);
            uint4 pack;
            pack.x = *reinterpret_cast<unsigned*>(&h0);
            pack.y = *reinterpret_cast<unsigned*>(&h1);
            pack.z = *reinterpret_cast<unsigned*>(&h2);
            pack.w = *reinterpret_cast<unsigned*>(&h3);
            *reinterpret_cast<uint4*>(&tile[(px * SY + py) * SZPH + c * 4]) = pack;
        }
    } else {
        // z-border: scalar, clamp baked into each pair.
        for (int idx = tid; idx < SX * SY * SZE; idx += 256) {
            int pz = idx % SZE;
            int r  = idx / SZE;
            int py = r % SY;
            int px = r / SY;
            int gx = iclamp(xlo + px, DX - 1);
            int gy = iclamp(ylo + py, DY - 1);
            const float* rowp = v + ((size_t)gx * DY + gy) * DZ;
            int gz0 = iclamp(zlo + pz,     DZ - 1);
            int gz1 = iclamp(zlo + pz + 1, DZ - 1);
            float a  = __ldg(rowp + gz0);
            float b2 = __ldg(rowp + gz1);
            tile[(px * SY + py) * SZPH + pz] = __floats2half2_rn(a, b2);
        }
    }
    __syncthreads();

    // ---------------- per-voxel warp, 4 z-voxels per thread ----------------
    const int zg = tid & 3;            // z quad (0..3)
    const int vy = (tid >> 2) & 15;    // 0..15
    const int xs = tid >> 6;           // 0..3
    const int gy = y0 + vy;
    const int zb = z0 + zg * 4;

    unsigned g = (unsigned)((((b * DX + x0 + xs) * DY + gy) * (DZ / 4))
                            + (z0 >> 2) + zg);
    const unsigned gstep = (unsigned)(DY * DZ);
    const float fgy = (float)gy;

    const float4* __restrict__ trf4 = reinterpret_cast<const float4*>(trf);
    float4* __restrict__ out4 = reinterpret_cast<float4*>(out);

#pragma unroll 1
    for (int it = 0; it < 4; ++it, g += gstep) {
        const float fgx = (float)(x0 + it * 4 + xs);

        float4 t0 = __ldg(&trf4[g * 3u + 0u]);
        float4 t1 = __ldg(&trf4[g * 3u + 1u]);
        float4 t2 = __ldg(&trf4[g * 3u + 2u]);

        float tx[4] = {t0.x, t0.w, t1.z, t2.y};
        float ty[4] = {t0.y, t1.x, t1.w, t2.z};
        float tz[4] = {t0.z, t1.y, t2.x, t2.w};

        float4 res;
        float* rp = reinterpret_cast<float*>(&res);

#pragma unroll
        for (int j = 0; j < 4; ++j) {
            // UNCLAMPED sample location
            float lx = fgx + tx[j];
            float ly = fgy + ty[j];
            float lz = (float)(zb + j) + tz[j];

            float fx0 = floorf(lx);
            float fy0 = floorf(ly);
            float fz0 = floorf(lz);

            // weights: wx0 = upper, wx1 = lower (exact; == reference in-tile)
            float wx0 = lx - fx0, wx1 = 1.0f - wx0;
            float wy0 = ly - fy0, wy1 = 1.0f - wy0;
            float wz0 = lz - fz0, wz1 = 1.0f - wz0;

            int ix0 = (int)fx0;
            int iy0 = (int)fy0;
            int iz0 = (int)fz0;

            unsigned sux = (unsigned)(ix0 - xlo);
            unsigned suy = (unsigned)(iy0 - ylo);
            unsigned suz = (unsigned)(iz0 - zlo);

            if (sux <= (unsigned)(SX - 2) &&
                suy <= (unsigned)(SY - 2) &&
                suz <= (unsigned)(SZE - 1)) {
                const __half2* t00 = &tile[(sux * SY + suy) * SZPH + suz];
                float2 f00 = __half22float2(t00[0]);
                float2 f01 = __half22float2(t00[SZPH]);            // +y
                float2 f10 = __half22float2(t00[SY * SZPH]);       // +x
                float2 f11 = __half22float2(t00[SY * SZPH + SZPH]);// +x+y
                float c00 = f00.x * wz1 + f00.y * wz0;
                float c01 = f01.x * wz1 + f01.y * wz0;
                float c10 = f10.x * wz1 + f10.y * wz0;
                float c11 = f11.x * wz1 + f11.y * wz0;
                float c0 = c00 * wy1 + c01 * wy0;
                float c1 = c10 * wy1 + c11 * wy0;
                rp[j] = c0 * wx1 + c1 * wx0;
            } else {
                rp[j] = fallback_exact(v, lx, ly, lz);
            }
        }

        out4[g] = res;
    }
}

extern "C" void kernel_launch(void* const* d_in, const int* in_sizes, int n_in,
                              void* d_out, int out_size)
{
    const float* vol = (const float*)d_in[0];
    const float* trf = (const float*)d_in[1];
    float* out = (float*)d_out;

    cudaFuncSetAttribute(warp_h2nc_kernel,
                         cudaFuncAttributeMaxDynamicSharedMemorySize,
                         SHALF2 * (int)sizeof(__half2));

    dim3 grid(DZ / TS, DY / TS, NB * (DX / TS));  // (10, 12, 20)
    warp_h2nc_kernel<<<grid, 256, SHALF2 * sizeof(__half2)>>>(vol, trf, out);
}